// round 1
// baseline (speedup 1.0000x reference)
#include <cuda_runtime.h>
#include <math.h>

#define NT 128
#define NB 256
#define NC 512
#define HID 256
#define EMB 128
#define NCLS 37
#define NSTEPS 25
#define POSE 256
#define RNN_IN (NC + EMB + POSE + 576)   // 1472
#define GRU3 (3 * HID)                   // 768

// ---------------- scratch (device globals; no allocs allowed) ----------------
__device__ float g_fp[NT * NB * HID];        // feats_proj (t,b,h)   32MB
__device__ float g_poseT[NT * NB * POSE];    // pose transposed      32MB
__device__ float g_hp[NB * HID];
__device__ float g_e[NT * NB];               // energies -> alpha (in place)
__device__ float g_x[NB * RNN_IN];           // [ctx | emb | crops]
__device__ float g_gi[NB * GRU3];
__device__ float g_gh[NB * GRU3];
__device__ float g_hidden[NB * HID];
__device__ float g_hs[NSTEPS * NB * HID];    // hs[(b*NSTEPS+s)*HID+h]

// ---------------- generic C = A @ B^T (+bias) register-tiled SGEMM ----------------
template<int BM, int BN, int BK, int TM, int TN>
__global__ void gemm_abt(const float* __restrict__ A, const float* __restrict__ B,
                         const float* __restrict__ bias, float* __restrict__ C,
                         int M, int N, int K)
{
    __shared__ float As[BK][BM + 1];
    __shared__ float Bs[BK][BN + 1];
    constexpr int THREADS = (BM / TM) * (BN / TN);
    const int tx = threadIdx.x;                 // 0..BN/TN-1
    const int ty = threadIdx.y;                 // 0..BM/TM-1
    const int tid = ty * (BN / TN) + tx;
    const int m0 = blockIdx.y * BM;
    const int n0 = blockIdx.x * BN;

    float acc[TM][TN];
#pragma unroll
    for (int i = 0; i < TM; i++)
#pragma unroll
        for (int j = 0; j < TN; j++) acc[i][j] = 0.f;

    for (int k0 = 0; k0 < K; k0 += BK) {
        for (int i = tid; i < BM * BK; i += THREADS) {
            int m = i / BK, k = i % BK;
            int gm = m0 + m, gk = k0 + k;
            As[k][m] = (gm < M && gk < K) ? A[(size_t)gm * K + gk] : 0.f;
        }
        for (int i = tid; i < BN * BK; i += THREADS) {
            int n = i / BK, k = i % BK;
            int gn = n0 + n, gk = k0 + k;
            Bs[k][n] = (gn < N && gk < K) ? B[(size_t)gn * K + gk] : 0.f;
        }
        __syncthreads();
#pragma unroll
        for (int k = 0; k < BK; k++) {
            float a[TM], bb[TN];
#pragma unroll
            for (int i = 0; i < TM; i++) a[i] = As[k][ty * TM + i];
#pragma unroll
            for (int j = 0; j < TN; j++) bb[j] = Bs[k][tx * TN + j];
#pragma unroll
            for (int i = 0; i < TM; i++)
#pragma unroll
                for (int j = 0; j < TN; j++) acc[i][j] += a[i] * bb[j];
        }
        __syncthreads();
    }
#pragma unroll
    for (int i = 0; i < TM; i++) {
        int gm = m0 + ty * TM + i;
        if (gm >= M) continue;
#pragma unroll
        for (int j = 0; j < TN; j++) {
            int gn = n0 + tx * TN + j;
            if (gn >= N) continue;
            C[(size_t)gm * N + gn] = acc[i][j] + (bias ? bias[gn] : 0.f);
        }
    }
}

// ---------------- init hidden to zero ----------------
__global__ void zero_hidden_kernel()
{
    int i = blockIdx.x * blockDim.x + threadIdx.x;
    if (i < NB * HID) g_hidden[i] = 0.f;
}

// ---------------- pose (NB,POSE,1,NT) -> poseT (NT,NB,POSE) ----------------
__global__ void pose_transpose_kernel(const float* __restrict__ pose)
{
    __shared__ float tile[32][33];
    int b = blockIdx.z;
    int p0 = blockIdx.x * 32;
    int t0 = blockIdx.y * 32;
    int x = threadIdx.x, y = threadIdx.y;
    // in[b, p0+y, t0+x]  (coalesced over t)
    tile[y][x] = pose[(size_t)b * POSE * NT + (size_t)(p0 + y) * NT + (t0 + x)];
    __syncthreads();
    // out[(t0+y)*NB + b, p0+x]  (coalesced over p)
    g_poseT[((size_t)(t0 + y) * NB + b) * POSE + (p0 + x)] = tile[x][y];
}

// ---------------- attention energy: e[t,b] = sum_h tanh(fp+hp)*sw ----------------
__global__ void attn_e_kernel(const float* __restrict__ sw)
{
    int gw = (blockIdx.x * blockDim.x + threadIdx.x) >> 5;
    int lane = threadIdx.x & 31;
    if (gw >= NT * NB) return;
    int t = gw / NB, b = gw % NB;
    const float* fprow = g_fp + ((size_t)t * NB + b) * HID;
    const float* hprow = g_hp + (size_t)b * HID;
    float s = 0.f;
#pragma unroll
    for (int h = lane; h < HID; h += 32)
        s += tanhf(fprow[h] + hprow[h]) * sw[h];
#pragma unroll
    for (int o = 16; o; o >>= 1) s += __shfl_xor_sync(0xffffffffu, s, o);
    if (!lane) g_e[t * NB + b] = s;
}

// ---------------- softmax over t (in-place in g_e) ----------------
__global__ void softmax_kernel()
{
    int b = blockIdx.x;
    int t = threadIdx.x;   // 128
    __shared__ float red[NT];
    float v = g_e[t * NB + b];
    red[t] = v; __syncthreads();
    for (int s = 64; s; s >>= 1) { if (t < s) red[t] = fmaxf(red[t], red[t + s]); __syncthreads(); }
    float mx = red[0]; __syncthreads();
    float ex = expf(v - mx);
    red[t] = ex; __syncthreads();
    for (int s = 64; s; s >>= 1) { if (t < s) red[t] += red[t + s]; __syncthreads(); }
    g_e[t * NB + b] = ex / red[0];
}

// ---------------- ctx[b,c] = sum_t alpha[t,b]*featcat[t,b,c] -> x[:, :768] ----------------
__global__ void ctx_kernel(const float* __restrict__ feats)
{
    int b = blockIdx.x;
    int c = threadIdx.x;   // 768
    __shared__ float al[NT];
    if (c < NT) al[c] = g_e[c * NB + b];
    __syncthreads();
    float acc = 0.f;
    if (c < NC) {
        const float* f = feats + (size_t)b * NC + c;
#pragma unroll 4
        for (int t = 0; t < NT; t++) acc += al[t] * f[(size_t)t * NB * NC];
    } else {
        const float* f = g_poseT + (size_t)b * POSE + (c - NC);
#pragma unroll 4
        for (int t = 0; t < NT; t++) acc += al[t] * f[(size_t)t * NB * POSE];
    }
    g_x[(size_t)b * RNN_IN + c] = acc;
}

// ---------------- per-step misc: coord, embedding, ROI crops -> x[:, 768:1472] ----------------
__global__ void step_misc_kernel(const float* __restrict__ pose_w,
                                 const float* __restrict__ pose_b,
                                 const float* __restrict__ pyr0,
                                 const float* __restrict__ pyr1,
                                 const float* __restrict__ pyr2,
                                 const int*   __restrict__ text,
                                 const float* __restrict__ char_emb,
                                 int step)
{
    int b = blockIdx.x;
    int tid = threadIdx.x;            // 128 threads
    int wid = tid >> 5, lane = tid & 31;

    __shared__ float s_coord[4];
    __shared__ float s_ly[3][2], s_lx[3][2];
    __shared__ int   s_y0[3][2], s_y1[3][2], s_x0[3][2], s_x1[3][2];
    __shared__ int   s_vy[3][2], s_vx[3][2];

    // coord = sigmoid(ctx @ pose_w^T + pose_b); ctx = x[b, :768]
    const float* ctx = g_x + (size_t)b * RNN_IN;
    if (wid < 4) {
        const float* pw = pose_w + wid * (NC + POSE);
        float s = 0.f;
        for (int c = lane; c < NC + POSE; c += 32) s += ctx[c] * pw[c];
#pragma unroll
        for (int o = 16; o; o >>= 1) s += __shfl_xor_sync(0xffffffffu, s, o);
        if (!lane) s_coord[wid] = 1.f / (1.f + expf(-(s + pose_b[wid])));
    }
    __syncthreads();

    if (tid == 0) {
        const int Hs[3] = {16, 8, 4};
        const int Ws[3] = {128, 64, 65};
        float c0 = s_coord[0], c1 = s_coord[1], c2 = s_coord[2], c3 = s_coord[3];
        for (int p = 0; p < 3; p++) {
            float Hf = (float)Hs[p], Wf = (float)Ws[p];
            // reference quirk: scale = [h, w, h, w] applied to [x1,y1,x2,y2], cumulative
            c0 *= Hf; c1 *= Wf; c2 *= Hf; c3 *= Wf;
            float x1 = c0, y1 = c1, x2 = c2, y2 = c3;
            float bw = fmaxf(x2 - x1, 1.f) * 0.5f;
            float bh = fmaxf(y2 - y1, 1.f) * 0.5f;
#pragma unroll
            for (int i = 0; i < 2; i++) {
                float ys = y1 + (0.5f + (float)i) * bh;
                s_vy[p][i] = (ys >= -1.f && ys <= Hf) ? 1 : 0;
                float y = fminf(fmaxf(ys, 0.f), Hf - 1.f);
                float y0f = floorf(y);
                int y0i = (int)y0f;
                s_y0[p][i] = y0i;
                s_y1[p][i] = min(y0i + 1, Hs[p] - 1);
                s_ly[p][i] = y - y0f;

                float xs = x1 + (0.5f + (float)i) * bw;
                s_vx[p][i] = (xs >= -1.f && xs <= Wf) ? 1 : 0;
                float x = fminf(fmaxf(xs, 0.f), Wf - 1.f);
                float x0f = floorf(x);
                int x0i = (int)x0f;
                s_x0[p][i] = x0i;
                s_x1[p][i] = min(x0i + 1, Ws[p] - 1);
                s_lx[p][i] = x - x0f;
            }
        }
    }

    // embedding
    int tgt = (step == 0) ? 0 : (text[b * NSTEPS + (step - 1)] + 1);
    for (int j = tid; j < EMB; j += blockDim.x)
        g_x[(size_t)b * RNN_IN + NC + POSE + j] = char_emb[tgt * EMB + j];

    __syncthreads();

    // crops: pyr0 -> 64, pyr1 -> 256, pyr2 -> 256
    for (int o = tid; o < 576; o += blockDim.x) {
        int p, local;
        if (o < 64)       { p = 0; local = o; }
        else if (o < 320) { p = 1; local = o - 64; }
        else              { p = 2; local = o - 320; }
        int c = local >> 2;
        int ij = local & 3;
        int i = ij >> 1, j = ij & 1;
        float val = 0.f;
        if (s_vy[p][i] && s_vx[p][j]) {
            float ly = s_ly[p][i], lx = s_lx[p][j];
            float hy = 1.f - ly, hx = 1.f - lx;
            int y0 = s_y0[p][i], y1 = s_y1[p][i];
            int x0 = s_x0[p][j], x1 = s_x1[p][j];
            const float* f; int H, W;
            if (p == 0)      { f = pyr0; H = 16; W = 128; }
            else if (p == 1) { f = pyr1; H = 8;  W = 64;  }
            else             { f = pyr2; H = 4;  W = 65;  }
            const float* fc = f + (size_t)c * H * W;   // batch 0 feature map
            val = fc[y0 * W + x0] * (hy * hx)
                + fc[y0 * W + x1] * (hy * lx)
                + fc[y1 * W + x0] * (ly * hx)
                + fc[y1 * W + x1] * (ly * lx);
        }
        g_x[(size_t)b * RNN_IN + NC + POSE + EMB + o] = val;
    }
}

// ---------------- GRU elementwise update ----------------
__global__ void gru_kernel(int step)
{
    int idx = blockIdx.x * blockDim.x + threadIdx.x;
    if (idx >= NB * HID) return;
    int b = idx / HID, h = idx % HID;
    const float* gi = g_gi + (size_t)b * GRU3;
    const float* gh = g_gh + (size_t)b * GRU3;
    float ir = gi[h],          hr = gh[h];
    float iz = gi[HID + h],    hz = gh[HID + h];
    float in = gi[2*HID + h],  hn = gh[2*HID + h];
    float r = 1.f / (1.f + expf(-(ir + hr)));
    float z = 1.f / (1.f + expf(-(iz + hz)));
    float n = tanhf(in + r * hn);
    float hold = g_hidden[idx];
    float hnew = (1.f - z) * n + z * hold;
    g_hidden[idx] = hnew;
    g_hs[((size_t)b * NSTEPS + step) * HID + h] = hnew;
}

// ---------------- final classifier: probs = hs @ gen_w^T + gen_b ----------------
__global__ void gen_kernel(const float* __restrict__ gen_w,
                           const float* __restrict__ gen_b,
                           float* __restrict__ out)
{
    int m = blockIdx.x;        // 6400 rows
    int tid = threadIdx.x;     // 256
    int wid = tid >> 5, lane = tid & 31;
    __shared__ float a[HID];
    a[tid] = g_hs[(size_t)m * HID + tid];
    __syncthreads();
    for (int n = wid; n < NCLS; n += 8) {
        const float* w = gen_w + n * HID;
        float s = 0.f;
#pragma unroll
        for (int k = lane; k < HID; k += 32) s += a[k] * w[k];
#pragma unroll
        for (int o = 16; o; o >>= 1) s += __shfl_xor_sync(0xffffffffu, s, o);
        if (!lane) out[(size_t)m * NCLS + n] = s + gen_b[n];
    }
}

// ---------------- driver ----------------
extern "C" void kernel_launch(void* const* d_in, const int* in_sizes, int n_in,
                              void* d_out, int out_size)
{
    const float* feats    = (const float*)d_in[0];
    const float* pose     = (const float*)d_in[1];
    const float* pyr0     = (const float*)d_in[2];
    const float* pyr1     = (const float*)d_in[3];
    const float* pyr2     = (const float*)d_in[4];
    const int*   text     = (const int*)  d_in[6];
    const float* i2h_w    = (const float*)d_in[7];
    const float* h2h_w    = (const float*)d_in[8];
    const float* h2h_b    = (const float*)d_in[9];
    const float* score_w  = (const float*)d_in[10];
    const float* pose_w   = (const float*)d_in[11];
    const float* pose_b   = (const float*)d_in[12];
    const float* gru_w_ih = (const float*)d_in[13];
    const float* gru_w_hh = (const float*)d_in[14];
    const float* gru_b_ih = (const float*)d_in[15];
    const float* gru_b_hh = (const float*)d_in[16];
    const float* char_emb = (const float*)d_in[17];
    const float* gen_w    = (const float*)d_in[18];
    const float* gen_b    = (const float*)d_in[19];
    float* out = (float*)d_out;

    float *p_fp, *p_hp, *p_e, *p_x, *p_gi, *p_gh, *p_hidden;
    cudaGetSymbolAddress((void**)&p_fp, g_fp);
    cudaGetSymbolAddress((void**)&p_hp, g_hp);
    cudaGetSymbolAddress((void**)&p_e, g_e);
    cudaGetSymbolAddress((void**)&p_x, g_x);
    cudaGetSymbolAddress((void**)&p_gi, g_gi);
    cudaGetSymbolAddress((void**)&p_gh, g_gh);
    cudaGetSymbolAddress((void**)&p_hidden, g_hidden);

    // hidden = 0
    zero_hidden_kernel<<<(NB * HID + 255) / 256, 256>>>();

    // pose transpose
    {
        dim3 grid(POSE / 32, NT / 32, NB);
        dim3 blk(32, 32);
        pose_transpose_kernel<<<grid, blk>>>(pose);
    }

    // feats_proj: (NT*NB, 512) @ (256, 512)^T
    {
        dim3 grid(HID / 64, (NT * NB) / 64);
        dim3 blk(16, 16);
        gemm_abt<64, 64, 32, 4, 4><<<grid, blk>>>(feats, i2h_w, nullptr, p_fp,
                                                  NT * NB, HID, NC);
    }

    for (int step = 0; step < NSTEPS; step++) {
        // hp = hidden @ h2h_w^T + h2h_b
        {
            dim3 grid(HID / 32, NB / 32);
            dim3 blk(16, 16);
            gemm_abt<32, 32, 32, 2, 2><<<grid, blk>>>(p_hidden, h2h_w, h2h_b, p_hp,
                                                      NB, HID, HID);
        }
        // e
        attn_e_kernel<<<(NT * NB) / 8, 256>>>(score_w);
        // softmax over t
        softmax_kernel<<<NB, NT>>>();
        // ctx -> x[:, :768]
        ctx_kernel<<<NB, NC + POSE>>>(feats);
        // coord + emb + crops -> x[:, 768:]
        step_misc_kernel<<<NB, 128>>>(pose_w, pose_b, pyr0, pyr1, pyr2, text,
                                      char_emb, step);
        // gi = x @ W_ih^T + b_ih
        {
            dim3 grid(GRU3 / 32, NB / 32);
            dim3 blk(16, 16);
            gemm_abt<32, 32, 32, 2, 2><<<grid, blk>>>(p_x, gru_w_ih, gru_b_ih, p_gi,
                                                      NB, GRU3, RNN_IN);
        }
        // gh = hidden @ W_hh^T + b_hh
        {
            dim3 grid(GRU3 / 32, NB / 32);
            dim3 blk(16, 16);
            gemm_abt<32, 32, 32, 2, 2><<<grid, blk>>>(p_hidden, gru_w_hh, gru_b_hh, p_gh,
                                                      NB, GRU3, HID);
        }
        // GRU update
        gru_kernel<<<(NB * HID + 255) / 256, 256>>>(step);
    }

    // final classifier
    gen_kernel<<<NB * NSTEPS, HID>>>(gen_w, gen_b, out);
}

// round 2
// speedup vs baseline: 2.0513x; 2.0513x over previous
#include <cuda_runtime.h>
#include <math.h>

#define NT 128
#define NB 256
#define NC 512
#define HID 256
#define EMB 128
#define NCLS 37
#define NSTEPS 25
#define POSE 256
#define RNN_IN 1472
#define GRU3 768
#define NCTA 592

// ---------------- scratch (device globals; no allocs allowed) ----------------
__device__ float g_fp[NT * NB * HID];
__device__ float g_poseT[NT * NB * POSE];
__device__ float g_hp[NB * HID];
__device__ float g_gh[NB * GRU3];
__device__ float g_x[NB * RNN_IN];
__device__ float g_gipart[4 * NB * GRU3];
__device__ float g_hidden[NB * HID];
__device__ float g_hs[NSTEPS * NB * HID];

__device__ unsigned g_arrive;
__device__ volatile unsigned g_release;

// sense-reversing grid barrier (all NCTA CTAs co-resident by construction)
__device__ __forceinline__ void gbar() {
    __threadfence();
    __syncthreads();
    if (threadIdx.x == 0) {
        unsigned gen = g_release;
        unsigned a = atomicAdd(&g_arrive, 1u);
        if (a == NCTA - 1u) {
            g_arrive = 0u;
            __threadfence();
            g_release = gen + 1u;
        } else {
            while (g_release == gen) __nanosleep(64);
        }
        __threadfence();
    }
    __syncthreads();
}

// ---------------- feats_proj: (32768,512) @ (256,512)^T -> g_fp ----------------
__global__ __launch_bounds__(256) void fp_gemm(const float* __restrict__ A,
                                               const float* __restrict__ B)
{
    __shared__ __align__(16) float As[16 * 132];
    __shared__ __align__(16) float Bs[16 * 132];
    const int tid = threadIdx.x;
    const int m0 = blockIdx.y * 128;
    const int n0 = blockIdx.x * 128;
    const int ty = tid >> 4, tx = tid & 15;
    float acc[8][8] = {};
    for (int k0 = 0; k0 < NC; k0 += 16) {
#pragma unroll
        for (int p = 0; p < 8; p++) {
            int i = p * 256 + tid;
            int kk = i & 15, mm = i >> 4;
            As[kk * 132 + mm] = A[(size_t)(m0 + mm) * NC + k0 + kk];
            Bs[kk * 132 + mm] = B[(size_t)(n0 + mm) * NC + k0 + kk];
        }
        __syncthreads();
#pragma unroll
        for (int k = 0; k < 16; k++) {
            float4 a0 = *(const float4*)&As[k * 132 + ty * 8];
            float4 a1 = *(const float4*)&As[k * 132 + ty * 8 + 4];
            float4 b0 = *(const float4*)&Bs[k * 132 + tx * 8];
            float4 b1 = *(const float4*)&Bs[k * 132 + tx * 8 + 4];
            float av[8] = {a0.x, a0.y, a0.z, a0.w, a1.x, a1.y, a1.z, a1.w};
            float bv[8] = {b0.x, b0.y, b0.z, b0.w, b1.x, b1.y, b1.z, b1.w};
#pragma unroll
            for (int i = 0; i < 8; i++)
#pragma unroll
                for (int j = 0; j < 8; j++) acc[i][j] += av[i] * bv[j];
        }
        __syncthreads();
    }
#pragma unroll
    for (int i = 0; i < 8; i++) {
        int gm = m0 + ty * 8 + i;
#pragma unroll
        for (int j = 0; j < 8; j++)
            g_fp[(size_t)gm * HID + n0 + tx * 8 + j] = acc[i][j];
    }
}

// ---------------- persistent decode kernel ----------------
__global__ __launch_bounds__(256, 4) void decode_kernel(
    const float* __restrict__ feats,
    const float* __restrict__ pose,
    const float* __restrict__ pyr0,
    const float* __restrict__ pyr1,
    const float* __restrict__ pyr2,
    const int*   __restrict__ text,
    const float* __restrict__ h2h_w,    const float* __restrict__ h2h_b,
    const float* __restrict__ score_w,
    const float* __restrict__ pose_w,   const float* __restrict__ pose_b,
    const float* __restrict__ gru_w_ih, const float* __restrict__ gru_w_hh,
    const float* __restrict__ gru_b_ih, const float* __restrict__ gru_b_hh,
    const float* __restrict__ char_emb,
    const float* __restrict__ gen_w,    const float* __restrict__ gen_b,
    float* __restrict__ out)
{
    __shared__ __align__(16) float sm[2176];
    __shared__ float s_coord[4];
    __shared__ float s_ly[3][2], s_lx[3][2];
    __shared__ int   s_y0[3][2], s_y1[3][2], s_x0[3][2], s_x1[3][2];
    __shared__ int   s_vy[3][2], s_vx[3][2];

    const int tid = threadIdx.x;
    const int bid = blockIdx.x;
    const int lane = tid & 31;
    const int wid = tid >> 5;

    // ---- prologue: hidden = 0, pose transpose (NB,POSE,1,NT) -> (NT,NB,POSE) ----
    {
        int g = bid * 256 + tid;
        if (g < NB * HID) g_hidden[g] = 0.f;
    }
    for (int job = bid; job < NB * 32; job += NCTA) {
        int b = job >> 5;
        int r = job & 31;
        int t0 = (r & 3) * 32;
        int p0 = (r >> 2) * 32;
        int y = tid >> 5, x = tid & 31;
#pragma unroll
        for (int q = 0; q < 4; q++) {
            int yy = y + q * 8;
            sm[yy * 33 + x] = pose[((size_t)b * POSE + (p0 + yy)) * NT + (t0 + x)];
        }
        __syncthreads();
#pragma unroll
        for (int q = 0; q < 4; q++) {
            int yy = y + q * 8;
            g_poseT[((size_t)(t0 + yy) * NB + b) * POSE + (p0 + x)] = sm[x * 33 + yy];
        }
        __syncthreads();
    }
    gbar();

    for (int step = 0; step < NSTEPS; step++) {
        // ================= P1: hp = hidden@h2h^T + b ; gh = hidden@Whh^T + b =====
        if (bid < 256) {
            const float* B; const float* bias; float* C; int N; int mt, nt;
            if (bid < 64) { B = h2h_w; bias = h2h_b; C = g_hp; N = HID; mt = bid >> 3; nt = bid & 7; }
            else { int jj = bid - 64; B = gru_w_hh; bias = gru_b_hh; C = g_gh; N = GRU3; mt = jj / 24; nt = jj % 24; }
            int m0 = mt * 32, n0 = nt * 32;
            float* As = sm; float* Bs = sm + 1056;
            int ty = tid >> 4, tx = tid & 15;
            float a00 = 0, a01 = 0, a10 = 0, a11 = 0;
            for (int k0 = 0; k0 < HID; k0 += 32) {
#pragma unroll
                for (int p = 0; p < 4; p++) {
                    int i = p * 256 + tid;
                    int kk = i & 31, mm = i >> 5;
                    As[kk * 33 + mm] = g_hidden[(size_t)(m0 + mm) * HID + k0 + kk];
                    Bs[kk * 33 + mm] = B[(size_t)(n0 + mm) * HID + k0 + kk];
                }
                __syncthreads();
#pragma unroll
                for (int k = 0; k < 32; k++) {
                    float av0 = As[k * 33 + ty * 2], av1 = As[k * 33 + ty * 2 + 1];
                    float bv0 = Bs[k * 33 + tx * 2], bv1 = Bs[k * 33 + tx * 2 + 1];
                    a00 += av0 * bv0; a01 += av0 * bv1; a10 += av1 * bv0; a11 += av1 * bv1;
                }
                __syncthreads();
            }
            int gm = m0 + ty * 2, gn = n0 + tx * 2;
            C[(size_t)gm * N + gn]           = a00 + bias[gn];
            C[(size_t)gm * N + gn + 1]       = a01 + bias[gn + 1];
            C[(size_t)(gm + 1) * N + gn]     = a10 + bias[gn];
            C[(size_t)(gm + 1) * N + gn + 1] = a11 + bias[gn + 1];
        }
        gbar();

        // ================= P2: per-b attention + ctx + coord + crops + emb ======
        if (bid < NB) {
            int b = bid;
            float* hp_s    = sm;
            float* e_s     = sm + 256;
            float* red     = sm + 384;
            float* alpha_s = sm + 512;
            float* ctx_s   = sm + 640;
            hp_s[tid] = g_hp[(size_t)b * HID + tid];
            __syncthreads();
            for (int t = wid; t < NT; t += 8) {
                const float* fp = g_fp + ((size_t)t * NB + b) * HID;
                float s = 0.f;
#pragma unroll
                for (int q = 0; q < 8; q++) {
                    int h = lane + q * 32;
                    s += tanhf(fp[h] + hp_s[h]) * score_w[h];
                }
#pragma unroll
                for (int o = 16; o; o >>= 1) s += __shfl_xor_sync(~0u, s, o);
                if (!lane) e_s[t] = s;
            }
            __syncthreads();
            if (tid < NT) red[tid] = e_s[tid];
            __syncthreads();
            for (int s = 64; s; s >>= 1) { if (tid < s) red[tid] = fmaxf(red[tid], red[tid + s]); __syncthreads(); }
            float mx = red[0];
            __syncthreads();
            if (tid < NT) { float ex = expf(e_s[tid] - mx); alpha_s[tid] = ex; red[tid] = ex; }
            __syncthreads();
            for (int s = 64; s; s >>= 1) { if (tid < s) red[tid] += red[tid + s]; __syncthreads(); }
            float inv = 1.f / red[0];
            __syncthreads();
            if (tid < NT) alpha_s[tid] *= inv;
            __syncthreads();
            // ctx over 768 channels (feats 512 + poseT 256)
            for (int c = tid; c < 768; c += 256) {
                const float* src; size_t stride;
                if (c < NC) { src = feats + (size_t)b * NC + c;            stride = (size_t)NB * NC; }
                else        { src = g_poseT + (size_t)b * POSE + (c - NC); stride = (size_t)NB * POSE; }
                float acc = 0.f;
#pragma unroll 8
                for (int t = 0; t < NT; t++) acc += alpha_s[t] * src[(size_t)t * stride];
                ctx_s[c] = acc;
                g_x[(size_t)b * RNN_IN + c] = acc;
            }
            __syncthreads();
            // coord = sigmoid(ctx @ pose_w^T + pose_b)
            if (wid < 4) {
                const float* pw = pose_w + wid * 768;
                float s = 0.f;
#pragma unroll
                for (int q = 0; q < 24; q++) { int c = lane + q * 32; s += ctx_s[c] * pw[c]; }
#pragma unroll
                for (int o = 16; o; o >>= 1) s += __shfl_xor_sync(~0u, s, o);
                if (!lane) s_coord[wid] = 1.f / (1.f + expf(-(s + pose_b[wid])));
            }
            // embedding
            int tgt = (step == 0) ? 0 : (text[b * NSTEPS + (step - 1)] + 1);
            if (tid < EMB) g_x[(size_t)b * RNN_IN + 768 + tid] = char_emb[(size_t)tgt * EMB + tid];
            __syncthreads();
            if (tid == 0) {
                const int Hs[3] = {16, 8, 4};
                const int Ws[3] = {128, 64, 65};
                float c0 = s_coord[0], c1 = s_coord[1], c2 = s_coord[2], c3 = s_coord[3];
                for (int p = 0; p < 3; p++) {
                    float Hf = (float)Hs[p], Wf = (float)Ws[p];
                    c0 *= Hf; c1 *= Wf; c2 *= Hf; c3 *= Wf;
                    float x1 = c0, y1 = c1, x2 = c2, y2 = c3;
                    float bw = fmaxf(x2 - x1, 1.f) * 0.5f;
                    float bh = fmaxf(y2 - y1, 1.f) * 0.5f;
#pragma unroll
                    for (int i = 0; i < 2; i++) {
                        float ys = y1 + (0.5f + (float)i) * bh;
                        s_vy[p][i] = (ys >= -1.f && ys <= Hf) ? 1 : 0;
                        float y = fminf(fmaxf(ys, 0.f), Hf - 1.f);
                        float y0f = floorf(y);
                        int y0i = (int)y0f;
                        s_y0[p][i] = y0i;
                        s_y1[p][i] = min(y0i + 1, Hs[p] - 1);
                        s_ly[p][i] = y - y0f;
                        float xs = x1 + (0.5f + (float)i) * bw;
                        s_vx[p][i] = (xs >= -1.f && xs <= Wf) ? 1 : 0;
                        float x = fminf(fmaxf(xs, 0.f), Wf - 1.f);
                        float x0f = floorf(x);
                        int x0i = (int)x0f;
                        s_x0[p][i] = x0i;
                        s_x1[p][i] = min(x0i + 1, Ws[p] - 1);
                        s_lx[p][i] = x - x0f;
                    }
                }
            }
            __syncthreads();
            for (int o = tid; o < 576; o += 256) {
                int p, local;
                if (o < 64)       { p = 0; local = o; }
                else if (o < 320) { p = 1; local = o - 64; }
                else              { p = 2; local = o - 320; }
                int c = local >> 2;
                int ij = local & 3;
                int i = ij >> 1, j = ij & 1;
                float val = 0.f;
                if (s_vy[p][i] && s_vx[p][j]) {
                    float ly = s_ly[p][i], lx = s_lx[p][j];
                    float hy = 1.f - ly, hx = 1.f - lx;
                    int y0 = s_y0[p][i], y1 = s_y1[p][i];
                    int x0 = s_x0[p][j], x1 = s_x1[p][j];
                    const float* f; int W;
                    if (p == 0)      { f = pyr0; W = 128; }
                    else if (p == 1) { f = pyr1; W = 64;  }
                    else             { f = pyr2; W = 65;  }
                    int HW = (p == 0) ? 16 * 128 : (p == 1 ? 8 * 64 : 4 * 65);
                    const float* fc = f + (size_t)c * HW;
                    val = fc[y0 * W + x0] * (hy * hx)
                        + fc[y0 * W + x1] * (hy * lx)
                        + fc[y1 * W + x0] * (ly * hx)
                        + fc[y1 * W + x1] * (ly * lx);
                }
                g_x[(size_t)b * RNN_IN + 896 + o] = val;
            }
        }
        gbar();

        // ================= P3: gi partials = x @ W_ih^T  (split-K 4) =============
        if (bid < 192) {
            int ks = bid / 48; int r = bid % 48; int mt = r / 12; int nt = r % 12;
            int m0 = mt * 64, n0 = nt * 64, kbase = ks * 368;
            float* As = sm; float* Bs = sm + 1088;
            int ty = tid >> 4, tx = tid & 15;
            float acc[4][4] = {};
            for (int kc = 0; kc < 368; kc += 16) {
#pragma unroll
                for (int p = 0; p < 4; p++) {
                    int i = p * 256 + tid;
                    int kk = i & 15, mm = i >> 4;
                    As[kk * 68 + mm] = g_x[(size_t)(m0 + mm) * RNN_IN + kbase + kc + kk];
                    Bs[kk * 68 + mm] = gru_w_ih[(size_t)(n0 + mm) * RNN_IN + kbase + kc + kk];
                }
                __syncthreads();
#pragma unroll
                for (int k = 0; k < 16; k++) {
                    float4 a0 = *(const float4*)&As[k * 68 + ty * 4];
                    float4 b0 = *(const float4*)&Bs[k * 68 + tx * 4];
                    float av[4] = {a0.x, a0.y, a0.z, a0.w};
                    float bv[4] = {b0.x, b0.y, b0.z, b0.w};
#pragma unroll
                    for (int i = 0; i < 4; i++)
#pragma unroll
                        for (int j = 0; j < 4; j++) acc[i][j] += av[i] * bv[j];
                }
                __syncthreads();
            }
            float* C = g_gipart + (size_t)ks * NB * GRU3;
#pragma unroll
            for (int i = 0; i < 4; i++) {
                int gm = m0 + ty * 4 + i;
#pragma unroll
                for (int j = 0; j < 4; j++)
                    C[(size_t)gm * GRU3 + n0 + tx * 4 + j] = acc[i][j];
            }
        }
        gbar();

        // ================= P4: reduce split-K + GRU update =======================
        {
            int g = bid * 256 + tid;
            if (g < NB * HID) {
                int b = g >> 8, h = g & 255;
                size_t base = (size_t)b * GRU3;
                const float* p0 = g_gipart;
                const float* p1 = g_gipart + (size_t)NB * GRU3;
                const float* p2 = g_gipart + 2 * (size_t)NB * GRU3;
                const float* p3 = g_gipart + 3 * (size_t)NB * GRU3;
                float ir = p0[base + h] + p1[base + h] + p2[base + h] + p3[base + h] + gru_b_ih[h];
                float iz = p0[base + HID + h] + p1[base + HID + h] + p2[base + HID + h] + p3[base + HID + h] + gru_b_ih[HID + h];
                float in = p0[base + 2 * HID + h] + p1[base + 2 * HID + h] + p2[base + 2 * HID + h] + p3[base + 2 * HID + h] + gru_b_ih[2 * HID + h];
                float hr = g_gh[base + h], hz = g_gh[base + HID + h], hn = g_gh[base + 2 * HID + h];
                float rr = 1.f / (1.f + expf(-(ir + hr)));
                float zz = 1.f / (1.f + expf(-(iz + hz)));
                float nn = tanhf(in + rr * hn);
                float hold = g_hidden[g];
                float hnew = (1.f - zz) * nn + zz * hold;
                g_hidden[g] = hnew;
                g_hs[((size_t)b * NSTEPS + step) * HID + h] = hnew;
            }
        }
        gbar();
    }

    // ================= final classifier ======================================
    {
        int gw = bid * 8 + wid;
        for (int m = gw; m < NB * NSTEPS; m += NCTA * 8) {
            const float* hrow = g_hs + (size_t)m * HID;
            float a[8];
#pragma unroll
            for (int q = 0; q < 8; q++) a[q] = hrow[lane + q * 32];
            for (int n = 0; n < NCLS; n++) {
                const float* w = gen_w + (size_t)n * HID;
                float s = 0.f;
#pragma unroll
                for (int q = 0; q < 8; q++) s += a[q] * w[lane + q * 32];
#pragma unroll
                for (int o = 16; o; o >>= 1) s += __shfl_xor_sync(~0u, s, o);
                if (!lane) out[(size_t)m * NCLS + n] = s + gen_b[n];
            }
        }
    }
}

// ---------------- driver ----------------
extern "C" void kernel_launch(void* const* d_in, const int* in_sizes, int n_in,
                              void* d_out, int out_size)
{
    const float* feats    = (const float*)d_in[0];
    const float* pose     = (const float*)d_in[1];
    const float* pyr0     = (const float*)d_in[2];
    const float* pyr1     = (const float*)d_in[3];
    const float* pyr2     = (const float*)d_in[4];
    const int*   text     = (const int*)  d_in[6];
    const float* i2h_w    = (const float*)d_in[7];
    const float* h2h_w    = (const float*)d_in[8];
    const float* h2h_b    = (const float*)d_in[9];
    const float* score_w  = (const float*)d_in[10];
    const float* pose_w   = (const float*)d_in[11];
    const float* pose_b   = (const float*)d_in[12];
    const float* gru_w_ih = (const float*)d_in[13];
    const float* gru_w_hh = (const float*)d_in[14];
    const float* gru_b_ih = (const float*)d_in[15];
    const float* gru_b_hh = (const float*)d_in[16];
    const float* char_emb = (const float*)d_in[17];
    const float* gen_w    = (const float*)d_in[18];
    const float* gen_b    = (const float*)d_in[19];
    float* out = (float*)d_out;

    // feats_proj (big parallel GEMM)
    dim3 g1(2, 256);
    fp_gemm<<<g1, 256>>>(feats, i2h_w);

    // persistent fused decode loop + classifier
    decode_kernel<<<NCTA, 256>>>(feats, pose, pyr0, pyr1, pyr2, text,
                                 h2h_w, h2h_b, score_w, pose_w, pose_b,
                                 gru_w_ih, gru_w_hh, gru_b_ih, gru_b_hh,
                                 char_emb, gen_w, gen_b, out);
}